// round 14
// baseline (speedup 1.0000x reference)
#include <cuda_runtime.h>
#include <math.h>

#define HB 65536   // H*B floats per t-slab
#define NU 2560    // 16-k-row units: L0 8 tiles x 64u, L1 8 x 128u, L2 8 x 128u
#define PAD 20     // smem row stride 80B: 16B-aligned float4 stores, conflict-free reads
#define UFLOATS (128 * PAD)   // floats per weight unit in smem (2560)

// ---- scratch ----
__device__ float g_WrA[3072 * 512];       // tf32 [j][k]: j<1024 Wi0+Ws0, <2048 Ws1, else Ws2
__device__ float g_Wr0[1024 * 1024];      // tf32 [n][k]  (Wh0)
__device__ float g_Wr1[1024 * 2048];      // [n][k] k<1024: Wi12[0], else Wh1
__device__ float g_Wr2[1024 * 2048];      // [n][k] k<1024: Wi12[1], else Wh2
__device__ float g_b0[1024], g_b1[1024], g_b2[1024];
__device__ float g_Xh[3 * 256 * 64 * 512];  // x-combination hi (tf32) [l][t][b][k]
__device__ float g_Xl[3 * 256 * 64 * 512];  // x-combination lo (tf32)
__device__ float g_A0[256 * HB], g_A1[256 * HB], g_A2[256 * HB];  // [t][b][h] fp32
__device__ float g_H0[257 * HB];          // [i][b][h]: H0[i]=h0[i-1] (tf32-rounded)
__device__ float g_H1[256 * HB];
__device__ float g_H2[256 * HB];
__device__ float g_P[320 * 2 * 8192];     // partials [blk][seg][b(64)][n(128)]
__device__ volatile unsigned g_flagA[512];  // per-block progress: gemm done for slot s -> s+1
__device__ volatile unsigned g_flagB[512];  // per-block progress: reduce done for slot s -> s+1

__device__ __forceinline__ float rnd_tf32(float x) {
    unsigned r;
    asm("cvt.rna.tf32.f32 %0, %1;" : "=r"(r) : "f"(x));
    return __uint_as_float(r);
}
__device__ __forceinline__ int ustart(int b, int nblk) {
    return (int)(((long long)b * NU) / nblk);
}

__global__ void prep_kernel(const float* __restrict__ Wi0, const float* __restrict__ Wi12,
                            const float* __restrict__ bi,  const float* __restrict__ Ws,
                            const float* __restrict__ bs,  const float* __restrict__ Wh,
                            const float* __restrict__ bh,  const float* __restrict__ noise) {
    int tid = blockIdx.x * blockDim.x + threadIdx.x, nthr = gridDim.x * blockDim.x;
    for (int i = tid; i < 3072 * 512; i += nthr) {
        int j = i >> 9, k = i & 511;
        float v;
        if (j < 1024)      v = Wi0[j * 512 + k] + Ws[j * 512 + k];
        else if (j < 2048) v = Ws[524288 + (j - 1024) * 512 + k];
        else               v = Ws[1048576 + (j - 2048) * 512 + k];
        g_WrA[i] = rnd_tf32(v);
    }
    for (int i = tid; i < 1024 * 1024; i += nthr)
        g_Wr0[i] = rnd_tf32(Wh[i]);
    for (int i = tid; i < 1024 * 2048; i += nthr) {
        int n = i >> 11, k = i & 2047;
        g_Wr1[i] = rnd_tf32((k < 1024) ? Wi12[n * 1024 + k] : Wh[1048576 + n * 1024 + (k - 1024)]);
        g_Wr2[i] = rnd_tf32((k < 1024) ? Wi12[1048576 + n * 1024 + k] : Wh[2097152 + n * 1024 + (k - 1024)]);
    }
    for (int i = tid; i < 1024; i += nthr) {
        g_b0[i] = bi[i] + bs[i] + bh[i];
        g_b1[i] = bi[1024 + i] + bs[1024 + i] + bh[1024 + i];
        g_b2[i] = bi[2048 + i] + bs[2048 + i] + bh[2048 + i];
    }
    for (int i = tid; i < 512; i += nthr) { g_flagA[i] = 0u; g_flagB[i] = 0u; }
    for (int i = tid; i < HB; i += nthr) {
        g_H0[i] = rnd_tf32(noise[i]);
        g_H1[i] = rnd_tf32(noise[3 * HB + i]);
        g_H2[2 * HB + i] = rnd_tf32(noise[6 * HB + i]);
    }
}

// xcomb: build shifted/scaled x combinations, split into tf32 hi+lo
__global__ void __launch_bounds__(256) xcomb_kernel(const float* __restrict__ x) {
    int idx = blockIdx.x * blockDim.x + threadIdx.x;
    if (idx >= 3 * 256 * 64 * 128) return;
    int l = idx / 2097152, rem = idx % 2097152;
    int t = rem >> 13, rem2 = rem & 8191;
    int b = rem2 >> 7, k4 = (rem2 & 127) * 4;
    const float* xb = x + b * 131072 + k4;
    float4 v = make_float4(0.f, 0.f, 0.f, 0.f);
    if (l == 0) {
        if (t + 3 < 256) v = *(const float4*)&xb[(t + 3) * 512];
    } else if (l == 1) {
        if (t + 2 < 256) { float4 u = *(const float4*)&xb[(t + 2) * 512]; v.x += u.x; v.y += u.y; v.z += u.z; v.w += u.w; }
        if (t + 3 < 256) { float4 u = *(const float4*)&xb[(t + 3) * 512]; v.x += u.x; v.y += u.y; v.z += u.z; v.w += u.w; }
        v.x *= 0.5f; v.y *= 0.5f; v.z *= 0.5f; v.w *= 0.5f;
    } else {
#pragma unroll
        for (int dt = 0; dt < 4; dt++)
            if (t + dt < 256) { float4 u = *(const float4*)&xb[(t + dt) * 512]; v.x += u.x; v.y += u.y; v.z += u.z; v.w += u.w; }
        v.x *= 0.25f; v.y *= 0.25f; v.z *= 0.25f; v.w *= 0.25f;
    }
    float4 hi = make_float4(rnd_tf32(v.x), rnd_tf32(v.y), rnd_tf32(v.z), rnd_tf32(v.w));
    float4 lo = make_float4(rnd_tf32(v.x - hi.x), rnd_tf32(v.y - hi.y),
                            rnd_tf32(v.z - hi.z), rnd_tf32(v.w - hi.w));
    int base = ((l * 16384) + t * 64 + b) * 512 + k4;
    *(float4*)&g_Xh[base] = hi;
    *(float4*)&g_Xl[base] = lo;
}

#define MMA_TF32(d, a, b) \
    asm volatile("mma.sync.aligned.m16n8k8.row.col.f32.tf32.tf32.f32 " \
                 "{%0,%1,%2,%3},{%4,%5,%6,%7},{%8,%9},{%0,%1,%2,%3};" \
                 : "+f"(d[0]), "+f"(d[1]), "+f"(d[2]), "+f"(d[3]) \
                 : "r"(a[0]), "r"(a[1]), "r"(a[2]), "r"(a[3]), "r"(b[0]), "r"(b[1]))

// A_l[t][b][h] = xc_l[t] @ WrA^T + bias_l  via tf32 mma, 2-term x-split
__global__ void __launch_bounds__(256) gemmA_mma_kernel() {
    __shared__ float Bs[128][PAD];
    __shared__ float Ah[64][PAD];
    __shared__ float Al[64][PAD];
    const int tid = threadIdx.x;
    const int warp = tid >> 5, lane = tid & 31;
    const int gid = lane >> 2, tig = lane & 3;
    const int hbase = blockIdx.x * 128, t = blockIdx.y, l = blockIdx.z;

    const int brow = tid >> 1, bhalf = tid & 1;
    const int arow = tid >> 2, aq = tid & 3;
    const float* bsrcT = g_WrA + (l * 1024 + hbase + brow) * 512 + bhalf * 8;
    const int xoff = ((l * 16384) + t * 64 + arow) * 512 + aq * 4;
    const float* xh = g_Xh + xoff;
    const float* xl = g_Xl + xoff;

    float acc[4][2][4];
#pragma unroll
    for (int mi = 0; mi < 4; mi++)
#pragma unroll
        for (int nj = 0; nj < 2; nj++)
#pragma unroll
            for (int q = 0; q < 4; q++) acc[mi][nj][q] = 0.f;

    float4 br0 = *(const float4*)(bsrcT);
    float4 br1 = *(const float4*)(bsrcT + 4);
    float4 ahv = *(const float4*)(xh);
    float4 alv = *(const float4*)(xl);
    for (int step = 0; step < 32; step++) {
        __syncthreads();
        *(float4*)&Bs[brow][bhalf * 8]     = br0;
        *(float4*)&Bs[brow][bhalf * 8 + 4] = br1;
        *(float4*)&Ah[arow][aq * 4]        = ahv;
        *(float4*)&Al[arow][aq * 4]        = alv;
        __syncthreads();
        if (step < 31) {
            int kn = (step + 1) * 16;
            br0 = *(const float4*)(bsrcT + kn);
            br1 = *(const float4*)(bsrcT + kn + 4);
            ahv = *(const float4*)(xh + kn);
            alv = *(const float4*)(xl + kn);
        }
#pragma unroll
        for (int sub = 0; sub < 2; sub++) {
            int ko = sub * 8 + tig;
            unsigned a[4][4], b[2][2];
#pragma unroll
            for (int nj = 0; nj < 2; nj++) {
                int n0 = warp * 16 + nj * 8 + gid;
                b[nj][0] = __float_as_uint(Bs[n0][ko]);
                b[nj][1] = __float_as_uint(Bs[n0][ko + 4]);
            }
#pragma unroll
            for (int mi = 0; mi < 4; mi++) {
                int r0 = mi * 16 + gid;
                a[mi][0] = __float_as_uint(Ah[r0][ko]);
                a[mi][1] = __float_as_uint(Ah[r0 + 8][ko]);
                a[mi][2] = __float_as_uint(Ah[r0][ko + 4]);
                a[mi][3] = __float_as_uint(Ah[r0 + 8][ko + 4]);
            }
#pragma unroll
            for (int mi = 0; mi < 4; mi++)
#pragma unroll
                for (int nj = 0; nj < 2; nj++) MMA_TF32(acc[mi][nj], a[mi], b[nj]);
#pragma unroll
            for (int mi = 0; mi < 4; mi++) {
                int r0 = mi * 16 + gid;
                a[mi][0] = __float_as_uint(Al[r0][ko]);
                a[mi][1] = __float_as_uint(Al[r0 + 8][ko]);
                a[mi][2] = __float_as_uint(Al[r0][ko + 4]);
                a[mi][3] = __float_as_uint(Al[r0 + 8][ko + 4]);
            }
#pragma unroll
            for (int mi = 0; mi < 4; mi++)
#pragma unroll
                for (int nj = 0; nj < 2; nj++) MMA_TF32(acc[mi][nj], a[mi], b[nj]);
        }
    }
    float* A = (l == 0) ? g_A0 : (l == 1) ? g_A1 : g_A2;
    const float* bl = (l == 0) ? g_b0 : (l == 1) ? g_b1 : g_b2;
#pragma unroll
    for (int mi = 0; mi < 4; mi++)
#pragma unroll
        for (int nj = 0; nj < 2; nj++) {
            int h = hbase + warp * 16 + nj * 8 + 2 * tig;
            float bv0 = bl[h], bv1 = bl[h + 1];
            int r = mi * 16 + gid;
            *(float2*)&A[t * HB + r * 1024 + h] =
                make_float2(acc[mi][nj][0] + bv0, acc[mi][nj][1] + bv1);
            *(float2*)&A[t * HB + (r + 8) * 1024 + h] =
                make_float2(acc[mi][nj][2] + bv0, acc[mi][nj][3] + bv1);
        }
}

// flag barrier: each block publishes its own progress; waiters poll all flags in parallel
__device__ __forceinline__ void gbar_flag(volatile unsigned* flags, int s, int nblk,
                                          int bid, int tid) {
    __syncthreads();
    if (tid == 0) {
        __threadfence();
        flags[bid] = (unsigned)(s + 1);
    }
    if (tid < nblk) {
        while (flags[tid] < (unsigned)(s + 1)) { }
    }
    __syncthreads();
    __threadfence();
}

__device__ __forceinline__ void tile_of(int u, int& layer, int& ntile, int& kst, int& tend) {
    if (u < 512)       { layer = 0; ntile = u >> 6; kst = (u & 63) * 16; tend = (ntile + 1) * 64; }
    else if (u < 1536) { int r = u - 512;  layer = 1; ntile = r >> 7; kst = (r & 127) * 16; tend = 512 + (ntile + 1) * 128; }
    else               { int r = u - 1536; layer = 2; ntile = r >> 7; kst = (r & 127) * 16; tend = 1536 + (ntile + 1) * 128; }
}

// Persistent recurrence: 512 threads/block, 1 block/SM, weights resident in smem.
// Warp tiling 2(m) x 8(n): A-fragments amortized over 2 nj -> 24 LDS/warp/step.
__global__ void __launch_bounds__(512) persist_kernel(int nblk) {
    extern __shared__ float sm_[];
    float* As_ = sm_;                 // double-buffered H staging: 2 x [64][PAD]
    float* Ws_ = sm_ + 2 * 64 * PAD;  // weight units, UFLOATS each
    __shared__ int tblP[24][24];
    __shared__ int tblCnt[24];
    const int tid = threadIdx.x, bid = blockIdx.x;
    const int warp = tid >> 5, lane = tid & 31;
    const int gid = lane >> 2, tig = lane & 3;
    const int wm = warp >> 3, wn = warp & 7;   // 2 x 8 warp grid
    const int u0 = ustart(bid, nblk), u1 = ustart(bid + 1, nblk);

    if (tid < 24) {
        int g = tid, t0, t1;
        if (g < 8)       { t0 = g * 64;                t1 = t0 + 64; }
        else if (g < 16) { t0 = 512 + (g - 8) * 128;   t1 = t0 + 128; }
        else             { t0 = 1536 + (g - 16) * 128; t1 = t0 + 128; }
        int cnt = 0;
        for (int bb = 0; bb < nblk; bb++) {
            int s0 = ustart(bb, nblk), s1 = ustart(bb + 1, nblk);
            if (s0 < t1 && s1 > t0) {
                int seg = (s0 < t0) ? 1 : 0;
                tblP[g][cnt++] = (bb * 2 + seg) * 8192;
            }
        }
        tblCnt[g] = cnt;
    }

    // ---- load this block's weight slab into smem (once) ----
    for (int j = 0; j < u1 - u0; j++) {
        int layer, ntile, kst, tend;
        tile_of(u0 + j, layer, ntile, kst, tend);
        const float* wsrc = (layer == 0) ? g_Wr0 : (layer == 1) ? g_Wr1 : g_Wr2;
        int K = (layer == 0) ? 1024 : 2048;
        int e = tid * 4, n = e >> 4, k0 = e & 15;
        float4 v = *(const float4*)&wsrc[(ntile * 128 + n) * K + kst + k0];
        *(float4*)&Ws_[j * UFLOATS + n * PAD + k0] = v;
    }
    __syncthreads();

    // precompute this thread's reduce-item geometry (static across slots)
    const int idx = bid * 512 + tid;
    const bool has_item = (idx < 49152);
    int r_g = 0, r_layer = 0, r_b = 0, r_nl4 = 0, r_nbase = 0;
    if (has_item) {
        r_g = idx >> 11;
        int e = idx & 2047;
        r_layer = r_g >> 3;
        r_b = e >> 5;
        r_nl4 = (e & 31) * 4;
        r_nbase = (r_g & 7) * 128;
    }

    int pp = 0;   // H-staging parity
    for (int s = 0; s < 258; s++) {
        // ---- prefetch reduce A input (independent of this slot's gemm) ----
        bool rvalid = false;
        float4 sumA;
        if (has_item) {
            rvalid = (r_layer == 0) ? (s <= 255)
                   : (r_layer == 1) ? (s >= 2 && s <= 256)
                                    : (s >= 5 && s <= 257);
            if (rvalid) {
                const float* A = (r_layer == 0) ? g_A0 : (r_layer == 1) ? g_A1 : g_A2;
                int t = (r_layer == 0) ? s : (r_layer == 1) ? (s - 1) : (s - 2);
                sumA = __ldcg((const float4*)&A[t * HB + r_b * 1024 + r_nbase + r_nl4]);
            }
        }

        // ================= GEMM phase =================
        int u = u0, seg = 0;
        while (u < u1) {
            int layer, ntile, kst, tend;
            tile_of(u, layer, ntile, kst, tend);
            int uend = (u1 < tend) ? u1 : tend;
            bool valid = (layer == 0) ? (s <= 255)
                       : (layer == 1) ? (s >= 2 && s <= 256)
                                      : (s >= 5 && s <= 257);
            if (valid) {
                const float *hA, *hB = 0;
                if (layer == 0)      { hA = g_H0 + s * HB; }
                else if (layer == 1) { hA = g_H0 + s * HB;       hB = g_H1 + (s - 2) * HB; }
                else                 { hA = g_H1 + (s - 2) * HB; hB = g_H2 + (s - 3) * HB; }

                const int arow = tid >> 2, aq = tid & 3;
                int steps = uend - u;
                int wbase = u - u0;

                auto ldH = [&](int kg) -> float4 {
                    return (layer == 0 || kg < 1024)
                         ? __ldcg((const float4*)(hA + arow * 1024 + kg))
                         : __ldcg((const float4*)(hB + arow * 1024 + kg - 1024));
                };

                float acc[2][2][4];
#pragma unroll
                for (int mi = 0; mi < 2; mi++)
#pragma unroll
                    for (int nj = 0; nj < 2; nj++)
#pragma unroll
                        for (int q = 0; q < 4; q++) acc[mi][nj][q] = 0.f;

                float4 arv0, arv1;
                if (tid < 256) {
                    arv0 = ldH(kst + aq * 4);
                    if (steps > 1) arv1 = ldH(kst + 16 + aq * 4);
                }
                for (int step = 0; step < steps; step++) {
                    if (tid < 256)
                        *(float4*)&As_[pp * 64 * PAD + arow * PAD + aq * 4] = arv0;
                    __syncthreads();
                    arv0 = arv1;
                    if (step + 2 < steps && tid < 256)
                        arv1 = ldH(kst + (step + 2) * 16 + aq * 4);
                    const float* wb = Ws_ + (wbase + step) * UFLOATS;
                    const float* ab = As_ + pp * 64 * PAD;
#pragma unroll
                    for (int sub = 0; sub < 2; sub++) {
                        int ko = sub * 8 + tig;
                        unsigned a[2][4], b[2][2];
#pragma unroll
                        for (int nj = 0; nj < 2; nj++) {
                            int n0 = wn * 16 + nj * 8 + gid;
                            b[nj][0] = __float_as_uint(wb[n0 * PAD + ko]);
                            b[nj][1] = __float_as_uint(wb[n0 * PAD + ko + 4]);
                        }
#pragma unroll
                        for (int mi = 0; mi < 2; mi++) {
                            int r0 = (wm * 2 + mi) * 16 + gid;
                            a[mi][0] = __float_as_uint(ab[r0 * PAD + ko]);
                            a[mi][1] = __float_as_uint(ab[(r0 + 8) * PAD + ko]);
                            a[mi][2] = __float_as_uint(ab[r0 * PAD + ko + 4]);
                            a[mi][3] = __float_as_uint(ab[(r0 + 8) * PAD + ko + 4]);
                        }
#pragma unroll
                        for (int mi = 0; mi < 2; mi++)
#pragma unroll
                            for (int nj = 0; nj < 2; nj++) MMA_TF32(acc[mi][nj], a[mi], b[nj]);
                    }
                    pp ^= 1;
                }
                float* pb = g_P + (bid * 2 + seg) * 8192;
#pragma unroll
                for (int mi = 0; mi < 2; mi++)
#pragma unroll
                    for (int nj = 0; nj < 2; nj++) {
                        int n = wn * 16 + nj * 8 + 2 * tig;
                        int b0 = (wm * 2 + mi) * 16 + gid;
                        *(float2*)&pb[b0 * 128 + n]       = make_float2(acc[mi][nj][0], acc[mi][nj][1]);
                        *(float2*)&pb[(b0 + 8) * 128 + n] = make_float2(acc[mi][nj][2], acc[mi][nj][3]);
                    }
            }
            u = uend;
            seg++;
        }
        gbar_flag(g_flagA, s, nblk, bid, tid);

        // ================= reduce phase (4-way MLP) =================
        if (rvalid) {
            float4 sum = sumA;
            float4 a1 = make_float4(0.f, 0.f, 0.f, 0.f);
            float4 a2 = make_float4(0.f, 0.f, 0.f, 0.f);
            float4 a3 = make_float4(0.f, 0.f, 0.f, 0.f);
            int cnt = tblCnt[r_g];
            int off = r_b * 128 + r_nl4;
            int j = 0;
            for (; j + 4 <= cnt; j += 4) {
                float4 p0 = __ldcg((const float4*)&g_P[tblP[r_g][j]     + off]);
                float4 p1 = __ldcg((const float4*)&g_P[tblP[r_g][j + 1] + off]);
                float4 p2 = __ldcg((const float4*)&g_P[tblP[r_g][j + 2] + off]);
                float4 p3 = __ldcg((const float4*)&g_P[tblP[r_g][j + 3] + off]);
                sum.x += p0.x; sum.y += p0.y; sum.z += p0.z; sum.w += p0.w;
                a1.x += p1.x; a1.y += p1.y; a1.z += p1.z; a1.w += p1.w;
                a2.x += p2.x; a2.y += p2.y; a2.z += p2.z; a2.w += p2.w;
                a3.x += p3.x; a3.y += p3.y; a3.z += p3.z; a3.w += p3.w;
            }
            for (; j < cnt; j++) {
                float4 p = __ldcg((const float4*)&g_P[tblP[r_g][j] + off]);
                sum.x += p.x; sum.y += p.y; sum.z += p.z; sum.w += p.w;
            }
            sum.x += a1.x + a2.x + a3.x;
            sum.y += a1.y + a2.y + a3.y;
            sum.z += a1.z + a2.z + a3.z;
            sum.w += a1.w + a2.w + a3.w;
            float* dst = (r_layer == 0) ? (g_H0 + (s + 1) * HB)
                       : (r_layer == 1) ? (g_H1 + (s - 1) * HB)
                                        : (g_H2 + (s - 2) * HB);
            *(float4*)&dst[r_b * 1024 + r_nbase + r_nl4] = make_float4(
                rnd_tf32(tanhf(sum.x)), rnd_tf32(tanhf(sum.y)),
                rnd_tf32(tanhf(sum.z)), rnd_tf32(tanhf(sum.w)));
        }
        gbar_flag(g_flagB, s, nblk, bid, tid);
    }
}

// out[l][b][i] = sum_h hs[b][h]*Wo[i][h] + bo[i]
__global__ void __launch_bounds__(256) out_kernel(const float* __restrict__ Wo,
                                                  const float* __restrict__ bo,
                                                  float* __restrict__ out) {
    __shared__ float Hs[64][65];
    __shared__ float Wos[32][65];
    const int l = blockIdx.y, ibase = blockIdx.x * 32;
    const float* hsrc = (l == 0) ? g_H0 + 256 * HB : (l == 1) ? g_H1 + 255 * HB : g_H2 + 255 * HB;
    const int tid = threadIdx.x, i = tid & 31, brow = tid >> 5;
    float acc[8];
#pragma unroll
    for (int q = 0; q < 8; q++) acc[q] = 0.f;
    for (int kc = 0; kc < 1024; kc += 64) {
        __syncthreads();
#pragma unroll
        for (int j = 0; j < 16; j++) {
            int e = j * 256 + tid, b = e >> 6, k = e & 63;
            Hs[b][k] = hsrc[b * 1024 + kc + k];
        }
#pragma unroll
        for (int j = 0; j < 8; j++) {
            int e = j * 256 + tid, ii = e >> 6, k = e & 63;
            Wos[ii][k] = Wo[(ibase + ii) * 1024 + kc + k];
        }
        __syncthreads();
#pragma unroll
        for (int k = 0; k < 64; k++) {
            float w = Wos[i][k];
#pragma unroll
            for (int bb = 0; bb < 8; bb++) acc[bb] += Hs[bb * 8 + brow][k] * w;
        }
    }
    float bv = bo[ibase + i];
#pragma unroll
    for (int bb = 0; bb < 8; bb++)
        out[l * 32768 + (bb * 8 + brow) * 512 + ibase + i] = acc[bb] + bv;
}

extern "C" void kernel_launch(void* const* d_in, const int* in_sizes, int n_in,
                              void* d_out, int out_size) {
    const float* x     = (const float*)d_in[0];
    const float* noise = (const float*)d_in[1];
    const float* Wi0   = (const float*)d_in[2];
    const float* Wi12  = (const float*)d_in[3];
    const float* bi    = (const float*)d_in[4];
    const float* Ws    = (const float*)d_in[5];
    const float* bs    = (const float*)d_in[6];
    const float* Wh    = (const float*)d_in[7];
    const float* bh    = (const float*)d_in[8];
    const float* Wo    = (const float*)d_in[9];
    const float* bo    = (const float*)d_in[10];
    float* out = (float*)d_out;

    int dev = 0, sm = 148;
    cudaGetDevice(&dev);
    cudaDeviceGetAttribute(&sm, cudaDevAttrMultiProcessorCount, dev);
    int nblk = sm;
    if (nblk > 296) nblk = 296;
    if (nblk < 1) nblk = 1;

    int maxu = (NU + nblk - 1) / nblk;            // max weight units per block
    size_t smemB = (size_t)(2 * 64 * PAD + (maxu + 1) * UFLOATS) * sizeof(float);
    static int smem_set = 0;
    if (!smem_set) {
        cudaFuncSetAttribute(persist_kernel,
                             cudaFuncAttributeMaxDynamicSharedMemorySize, (int)smemB);
        smem_set = 1;
    }

    prep_kernel<<<512, 256>>>(Wi0, Wi12, bi, Ws, bs, Wh, bh, noise);
    xcomb_kernel<<<24576, 256>>>(x);
    gemmA_mma_kernel<<<dim3(8, 256, 3), 256>>>();
    persist_kernel<<<nblk, 512, smemB>>>(nblk);
    out_kernel<<<dim3(16, 3), 256>>>(Wo, bo, out);
}

// round 15
// speedup vs baseline: 1.3164x; 1.3164x over previous
#include <cuda_runtime.h>
#include <math.h>

#define HB 65536   // H*B floats per t-slab
#define NU 2560    // 16-k-row units: L0 8 tiles x 64u, L1 8 x 128u, L2 8 x 128u
#define PAD 20     // smem row stride 80B: 16B-aligned float4 stores, conflict-free reads
#define UFLOATS (128 * PAD)   // floats per weight unit in smem (2560)

// ---- scratch ----
__device__ float g_WrA[3072 * 512];       // tf32 [j][k]: j<1024 Wi0+Ws0, <2048 Ws1, else Ws2
__device__ float g_Wr0[1024 * 1024];      // tf32 [n][k]  (Wh0)
__device__ float g_Wr1[1024 * 2048];      // [n][k] k<1024: Wi12[0], else Wh1
__device__ float g_Wr2[1024 * 2048];      // [n][k] k<1024: Wi12[1], else Wh2
__device__ float g_b0[1024], g_b1[1024], g_b2[1024];
__device__ float g_Xh[3 * 256 * 64 * 512];  // x-combination hi (tf32) [l][t][b][k]
__device__ float g_Xl[3 * 256 * 64 * 512];  // x-combination lo (tf32)
__device__ float g_A0[256 * HB], g_A1[256 * HB], g_A2[256 * HB];  // [t][b][h] fp32
__device__ float g_H0[257 * HB];          // [i][b][h]: H0[i]=h0[i-1] (tf32-rounded)
__device__ float g_H1[256 * HB];
__device__ float g_H2[256 * HB];
__device__ float g_P[320 * 2 * 8192];     // partials [blk][seg][b(64)][n(128)]
__device__ unsigned g_bar[516];

__device__ __forceinline__ float rnd_tf32(float x) {
    unsigned r;
    asm("cvt.rna.tf32.f32 %0, %1;" : "=r"(r) : "f"(x));
    return __uint_as_float(r);
}
__device__ __forceinline__ int ustart(int b, int nblk) {
    return (int)(((long long)b * NU) / nblk);
}

__global__ void prep_kernel(const float* __restrict__ Wi0, const float* __restrict__ Wi12,
                            const float* __restrict__ bi,  const float* __restrict__ Ws,
                            const float* __restrict__ bs,  const float* __restrict__ Wh,
                            const float* __restrict__ bh,  const float* __restrict__ noise) {
    int tid = blockIdx.x * blockDim.x + threadIdx.x, nthr = gridDim.x * blockDim.x;
    for (int i = tid; i < 3072 * 512; i += nthr) {
        int j = i >> 9, k = i & 511;
        float v;
        if (j < 1024)      v = Wi0[j * 512 + k] + Ws[j * 512 + k];
        else if (j < 2048) v = Ws[524288 + (j - 1024) * 512 + k];
        else               v = Ws[1048576 + (j - 2048) * 512 + k];
        g_WrA[i] = rnd_tf32(v);
    }
    for (int i = tid; i < 1024 * 1024; i += nthr)
        g_Wr0[i] = rnd_tf32(Wh[i]);
    for (int i = tid; i < 1024 * 2048; i += nthr) {
        int n = i >> 11, k = i & 2047;
        g_Wr1[i] = rnd_tf32((k < 1024) ? Wi12[n * 1024 + k] : Wh[1048576 + n * 1024 + (k - 1024)]);
        g_Wr2[i] = rnd_tf32((k < 1024) ? Wi12[1048576 + n * 1024 + k] : Wh[2097152 + n * 1024 + (k - 1024)]);
    }
    for (int i = tid; i < 1024; i += nthr) {
        g_b0[i] = bi[i] + bs[i] + bh[i];
        g_b1[i] = bi[1024 + i] + bs[1024 + i] + bh[1024 + i];
        g_b2[i] = bi[2048 + i] + bs[2048 + i] + bh[2048 + i];
    }
    for (int i = tid; i < 516; i += nthr) g_bar[i] = 0u;
    for (int i = tid; i < HB; i += nthr) {
        g_H0[i] = rnd_tf32(noise[i]);
        g_H1[i] = rnd_tf32(noise[3 * HB + i]);
        g_H2[2 * HB + i] = rnd_tf32(noise[6 * HB + i]);
    }
}

// xcomb: build shifted/scaled x combinations, split into tf32 hi+lo
__global__ void __launch_bounds__(256) xcomb_kernel(const float* __restrict__ x) {
    int idx = blockIdx.x * blockDim.x + threadIdx.x;
    if (idx >= 3 * 256 * 64 * 128) return;
    int l = idx / 2097152, rem = idx % 2097152;
    int t = rem >> 13, rem2 = rem & 8191;
    int b = rem2 >> 7, k4 = (rem2 & 127) * 4;
    const float* xb = x + b * 131072 + k4;
    float4 v = make_float4(0.f, 0.f, 0.f, 0.f);
    if (l == 0) {
        if (t + 3 < 256) v = *(const float4*)&xb[(t + 3) * 512];
    } else if (l == 1) {
        if (t + 2 < 256) { float4 u = *(const float4*)&xb[(t + 2) * 512]; v.x += u.x; v.y += u.y; v.z += u.z; v.w += u.w; }
        if (t + 3 < 256) { float4 u = *(const float4*)&xb[(t + 3) * 512]; v.x += u.x; v.y += u.y; v.z += u.z; v.w += u.w; }
        v.x *= 0.5f; v.y *= 0.5f; v.z *= 0.5f; v.w *= 0.5f;
    } else {
#pragma unroll
        for (int dt = 0; dt < 4; dt++)
            if (t + dt < 256) { float4 u = *(const float4*)&xb[(t + dt) * 512]; v.x += u.x; v.y += u.y; v.z += u.z; v.w += u.w; }
        v.x *= 0.25f; v.y *= 0.25f; v.z *= 0.25f; v.w *= 0.25f;
    }
    float4 hi = make_float4(rnd_tf32(v.x), rnd_tf32(v.y), rnd_tf32(v.z), rnd_tf32(v.w));
    float4 lo = make_float4(rnd_tf32(v.x - hi.x), rnd_tf32(v.y - hi.y),
                            rnd_tf32(v.z - hi.z), rnd_tf32(v.w - hi.w));
    int base = ((l * 16384) + t * 64 + b) * 512 + k4;
    *(float4*)&g_Xh[base] = hi;
    *(float4*)&g_Xl[base] = lo;
}

#define MMA_TF32(d, a, b) \
    asm volatile("mma.sync.aligned.m16n8k8.row.col.f32.tf32.tf32.f32 " \
                 "{%0,%1,%2,%3},{%4,%5,%6,%7},{%8,%9},{%0,%1,%2,%3};" \
                 : "+f"(d[0]), "+f"(d[1]), "+f"(d[2]), "+f"(d[3]) \
                 : "r"(a[0]), "r"(a[1]), "r"(a[2]), "r"(a[3]), "r"(b[0]), "r"(b[1]))

// A_l[t][b][h] = xc_l[t] @ WrA^T + bias_l  via tf32 mma, 2-term x-split
__global__ void __launch_bounds__(256) gemmA_mma_kernel() {
    __shared__ float Bs[128][PAD];
    __shared__ float Ah[64][PAD];
    __shared__ float Al[64][PAD];
    const int tid = threadIdx.x;
    const int warp = tid >> 5, lane = tid & 31;
    const int gid = lane >> 2, tig = lane & 3;
    const int hbase = blockIdx.x * 128, t = blockIdx.y, l = blockIdx.z;

    const int brow = tid >> 1, bhalf = tid & 1;
    const int arow = tid >> 2, aq = tid & 3;
    const float* bsrcT = g_WrA + (l * 1024 + hbase + brow) * 512 + bhalf * 8;
    const int xoff = ((l * 16384) + t * 64 + arow) * 512 + aq * 4;
    const float* xh = g_Xh + xoff;
    const float* xl = g_Xl + xoff;

    float acc[4][2][4];
#pragma unroll
    for (int mi = 0; mi < 4; mi++)
#pragma unroll
        for (int nj = 0; nj < 2; nj++)
#pragma unroll
            for (int q = 0; q < 4; q++) acc[mi][nj][q] = 0.f;

    float4 br0 = *(const float4*)(bsrcT);
    float4 br1 = *(const float4*)(bsrcT + 4);
    float4 ahv = *(const float4*)(xh);
    float4 alv = *(const float4*)(xl);
    for (int step = 0; step < 32; step++) {
        __syncthreads();
        *(float4*)&Bs[brow][bhalf * 8]     = br0;
        *(float4*)&Bs[brow][bhalf * 8 + 4] = br1;
        *(float4*)&Ah[arow][aq * 4]        = ahv;
        *(float4*)&Al[arow][aq * 4]        = alv;
        __syncthreads();
        if (step < 31) {
            int kn = (step + 1) * 16;
            br0 = *(const float4*)(bsrcT + kn);
            br1 = *(const float4*)(bsrcT + kn + 4);
            ahv = *(const float4*)(xh + kn);
            alv = *(const float4*)(xl + kn);
        }
#pragma unroll
        for (int sub = 0; sub < 2; sub++) {
            int ko = sub * 8 + tig;
            unsigned a[4][4], b[2][2];
#pragma unroll
            for (int nj = 0; nj < 2; nj++) {
                int n0 = warp * 16 + nj * 8 + gid;
                b[nj][0] = __float_as_uint(Bs[n0][ko]);
                b[nj][1] = __float_as_uint(Bs[n0][ko + 4]);
            }
#pragma unroll
            for (int mi = 0; mi < 4; mi++) {
                int r0 = mi * 16 + gid;
                a[mi][0] = __float_as_uint(Ah[r0][ko]);
                a[mi][1] = __float_as_uint(Ah[r0 + 8][ko]);
                a[mi][2] = __float_as_uint(Ah[r0][ko + 4]);
                a[mi][3] = __float_as_uint(Ah[r0 + 8][ko + 4]);
            }
#pragma unroll
            for (int mi = 0; mi < 4; mi++)
#pragma unroll
                for (int nj = 0; nj < 2; nj++) MMA_TF32(acc[mi][nj], a[mi], b[nj]);
#pragma unroll
            for (int mi = 0; mi < 4; mi++) {
                int r0 = mi * 16 + gid;
                a[mi][0] = __float_as_uint(Al[r0][ko]);
                a[mi][1] = __float_as_uint(Al[r0 + 8][ko]);
                a[mi][2] = __float_as_uint(Al[r0][ko + 4]);
                a[mi][3] = __float_as_uint(Al[r0 + 8][ko + 4]);
            }
#pragma unroll
            for (int mi = 0; mi < 4; mi++)
#pragma unroll
                for (int nj = 0; nj < 2; nj++) MMA_TF32(acc[mi][nj], a[mi], b[nj]);
        }
    }
    float* A = (l == 0) ? g_A0 : (l == 1) ? g_A1 : g_A2;
    const float* bl = (l == 0) ? g_b0 : (l == 1) ? g_b1 : g_b2;
#pragma unroll
    for (int mi = 0; mi < 4; mi++)
#pragma unroll
        for (int nj = 0; nj < 2; nj++) {
            int h = hbase + warp * 16 + nj * 8 + 2 * tig;
            float bv0 = bl[h], bv1 = bl[h + 1];
            int r = mi * 16 + gid;
            *(float2*)&A[t * HB + r * 1024 + h] =
                make_float2(acc[mi][nj][0] + bv0, acc[mi][nj][1] + bv1);
            *(float2*)&A[t * HB + (r + 8) * 1024 + h] =
                make_float2(acc[mi][nj][2] + bv0, acc[mi][nj][3] + bv1);
        }
}

__device__ __forceinline__ void gbar(int i, int nblk) {
    __syncthreads();
    if (threadIdx.x == 0) {
        __threadfence();
        atomicAdd(&g_bar[i], 1u);
        while (*((volatile unsigned*)&g_bar[i]) < (unsigned)nblk) { }
        __threadfence();
    }
    __syncthreads();
}

__device__ __forceinline__ void tile_of(int u, int& layer, int& ntile, int& kst, int& tend) {
    if (u < 512)       { layer = 0; ntile = u >> 6; kst = (u & 63) * 16; tend = (ntile + 1) * 64; }
    else if (u < 1536) { int r = u - 512;  layer = 1; ntile = r >> 7; kst = (r & 127) * 16; tend = 512 + (ntile + 1) * 128; }
    else               { int r = u - 1536; layer = 2; ntile = r >> 7; kst = (r & 127) * 16; tend = 1536 + (ntile + 1) * 128; }
}

// Persistent recurrence: 512 threads/block, 1 block/SM, weights resident in smem.
// Warp tiling 2(m) x 8(n): 24 LDS/warp/step instead of 36.
__global__ void __launch_bounds__(512) persist_kernel(int nblk) {
    extern __shared__ float sm_[];
    float* As_ = sm_;                 // double-buffered H staging: 2 x [64][PAD]
    float* Ws_ = sm_ + 2 * 64 * PAD;  // weight units, UFLOATS each
    __shared__ int tblP[24][24];
    __shared__ int tblCnt[24];
    const int tid = threadIdx.x, bid = blockIdx.x;
    const int warp = tid >> 5, lane = tid & 31;
    const int gid = lane >> 2, tig = lane & 3;
    const int wm = warp >> 3, wn = warp & 7;   // 2 x 8 warp grid
    const int u0 = ustart(bid, nblk), u1 = ustart(bid + 1, nblk);

    if (tid < 24) {
        int g = tid, t0, t1;
        if (g < 8)       { t0 = g * 64;                t1 = t0 + 64; }
        else if (g < 16) { t0 = 512 + (g - 8) * 128;   t1 = t0 + 128; }
        else             { t0 = 1536 + (g - 16) * 128; t1 = t0 + 128; }
        int cnt = 0;
        for (int bb = 0; bb < nblk; bb++) {
            int s0 = ustart(bb, nblk), s1 = ustart(bb + 1, nblk);
            if (s0 < t1 && s1 > t0) {
                int seg = (s0 < t0) ? 1 : 0;
                tblP[g][cnt++] = (bb * 2 + seg) * 8192;
            }
        }
        tblCnt[g] = cnt;
    }

    // ---- load this block's weight slab into smem (once) ----
    for (int j = 0; j < u1 - u0; j++) {
        int layer, ntile, kst, tend;
        tile_of(u0 + j, layer, ntile, kst, tend);
        const float* wsrc = (layer == 0) ? g_Wr0 : (layer == 1) ? g_Wr1 : g_Wr2;
        int K = (layer == 0) ? 1024 : 2048;
        int e = tid * 4, n = e >> 4, k0 = e & 15;
        float4 v = *(const float4*)&wsrc[(ntile * 128 + n) * K + kst + k0];
        *(float4*)&Ws_[j * UFLOATS + n * PAD + k0] = v;
    }
    __syncthreads();

    // precompute this thread's reduce-item geometry (static across slots)
    const int idx = bid * 512 + tid;
    const bool has_item = (idx < 49152);
    int r_g = 0, r_layer = 0, r_b = 0, r_nl4 = 0, r_nbase = 0;
    if (has_item) {
        r_g = idx >> 11;
        int e = idx & 2047;
        r_layer = r_g >> 3;
        r_b = e >> 5;
        r_nl4 = (e & 31) * 4;
        r_nbase = (r_g & 7) * 128;
    }

    int pp = 0;   // H-staging parity
    for (int s = 0; s < 258; s++) {
        // ---- prefetch reduce A input (independent of this slot's gemm) ----
        bool rvalid = false;
        float4 sumA;
        if (has_item) {
            rvalid = (r_layer == 0) ? (s <= 255)
                   : (r_layer == 1) ? (s >= 2 && s <= 256)
                                    : (s >= 5 && s <= 257);
            if (rvalid) {
                const float* A = (r_layer == 0) ? g_A0 : (r_layer == 1) ? g_A1 : g_A2;
                int t = (r_layer == 0) ? s : (r_layer == 1) ? (s - 1) : (s - 2);
                sumA = __ldcg((const float4*)&A[t * HB + r_b * 1024 + r_nbase + r_nl4]);
            }
        }

        // ================= GEMM phase =================
        int u = u0, seg = 0;
        while (u < u1) {
            int layer, ntile, kst, tend;
            tile_of(u, layer, ntile, kst, tend);
            int uend = (u1 < tend) ? u1 : tend;
            bool valid = (layer == 0) ? (s <= 255)
                       : (layer == 1) ? (s >= 2 && s <= 256)
                                      : (s >= 5 && s <= 257);
            if (valid) {
                const float *hA, *hB = 0;
                if (layer == 0)      { hA = g_H0 + s * HB; }
                else if (layer == 1) { hA = g_H0 + s * HB;       hB = g_H1 + (s - 2) * HB; }
                else                 { hA = g_H1 + (s - 2) * HB; hB = g_H2 + (s - 3) * HB; }

                const int arow = tid >> 2, aq = tid & 3;
                int steps = uend - u;
                int wbase = u - u0;

                auto ldH = [&](int kg) -> float4 {
                    return (layer == 0 || kg < 1024)
                         ? __ldcg((const float4*)(hA + arow * 1024 + kg))
                         : __ldcg((const float4*)(hB + arow * 1024 + kg - 1024));
                };

                float acc[2][2][4];
#pragma unroll
                for (int mi = 0; mi < 2; mi++)
#pragma unroll
                    for (int nj = 0; nj < 2; nj++)
#pragma unroll
                        for (int q = 0; q < 4; q++) acc[mi][nj][q] = 0.f;

                float4 arv0, arv1;
                if (tid < 256) {
                    arv0 = ldH(kst + aq * 4);
                    if (steps > 1) arv1 = ldH(kst + 16 + aq * 4);
                }
                for (int step = 0; step < steps; step++) {
                    if (tid < 256)
                        *(float4*)&As_[pp * 64 * PAD + arow * PAD + aq * 4] = arv0;
                    __syncthreads();
                    arv0 = arv1;
                    if (step + 2 < steps && tid < 256)
                        arv1 = ldH(kst + (step + 2) * 16 + aq * 4);
                    const float* wb = Ws_ + (wbase + step) * UFLOATS;
                    const float* ab = As_ + pp * 64 * PAD;
#pragma unroll
                    for (int sub = 0; sub < 2; sub++) {
                        int ko = sub * 8 + tig;
                        unsigned a[2][4], b[2][2];
#pragma unroll
                        for (int nj = 0; nj < 2; nj++) {
                            int n0 = wn * 16 + nj * 8 + gid;
                            b[nj][0] = __float_as_uint(wb[n0 * PAD + ko]);
                            b[nj][1] = __float_as_uint(wb[n0 * PAD + ko + 4]);
                        }
#pragma unroll
                        for (int mi = 0; mi < 2; mi++) {
                            int r0 = (wm * 2 + mi) * 16 + gid;
                            a[mi][0] = __float_as_uint(ab[r0 * PAD + ko]);
                            a[mi][1] = __float_as_uint(ab[(r0 + 8) * PAD + ko]);
                            a[mi][2] = __float_as_uint(ab[r0 * PAD + ko + 4]);
                            a[mi][3] = __float_as_uint(ab[(r0 + 8) * PAD + ko + 4]);
                        }
#pragma unroll
                        for (int mi = 0; mi < 2; mi++)
#pragma unroll
                            for (int nj = 0; nj < 2; nj++) MMA_TF32(acc[mi][nj], a[mi], b[nj]);
                    }
                    pp ^= 1;
                }
                float* pb = g_P + (bid * 2 + seg) * 8192;
#pragma unroll
                for (int mi = 0; mi < 2; mi++)
#pragma unroll
                    for (int nj = 0; nj < 2; nj++) {
                        int n = wn * 16 + nj * 8 + 2 * tig;
                        int b0 = (wm * 2 + mi) * 16 + gid;
                        *(float2*)&pb[b0 * 128 + n]       = make_float2(acc[mi][nj][0], acc[mi][nj][1]);
                        *(float2*)&pb[(b0 + 8) * 128 + n] = make_float2(acc[mi][nj][2], acc[mi][nj][3]);
                    }
            }
            u = uend;
            seg++;
        }
        gbar(2 * s, nblk);

        // ================= reduce phase (4-way MLP) =================
        if (rvalid) {
            float4 sum = sumA;
            float4 a1 = make_float4(0.f, 0.f, 0.f, 0.f);
            float4 a2 = make_float4(0.f, 0.f, 0.f, 0.f);
            float4 a3 = make_float4(0.f, 0.f, 0.f, 0.f);
            int cnt = tblCnt[r_g];
            int off = r_b * 128 + r_nl4;
            int j = 0;
            for (; j + 4 <= cnt; j += 4) {
                float4 p0 = __ldcg((const float4*)&g_P[tblP[r_g][j]     + off]);
                float4 p1 = __ldcg((const float4*)&g_P[tblP[r_g][j + 1] + off]);
                float4 p2 = __ldcg((const float4*)&g_P[tblP[r_g][j + 2] + off]);
                float4 p3 = __ldcg((const float4*)&g_P[tblP[r_g][j + 3] + off]);
                sum.x += p0.x; sum.y += p0.y; sum.z += p0.z; sum.w += p0.w;
                a1.x += p1.x; a1.y += p1.y; a1.z += p1.z; a1.w += p1.w;
                a2.x += p2.x; a2.y += p2.y; a2.z += p2.z; a2.w += p2.w;
                a3.x += p3.x; a3.y += p3.y; a3.z += p3.z; a3.w += p3.w;
            }
            for (; j < cnt; j++) {
                float4 p = __ldcg((const float4*)&g_P[tblP[r_g][j] + off]);
                sum.x += p.x; sum.y += p.y; sum.z += p.z; sum.w += p.w;
            }
            sum.x += a1.x + a2.x + a3.x;
            sum.y += a1.y + a2.y + a3.y;
            sum.z += a1.z + a2.z + a3.z;
            sum.w += a1.w + a2.w + a3.w;
            float* dst = (r_layer == 0) ? (g_H0 + (s + 1) * HB)
                       : (r_layer == 1) ? (g_H1 + (s - 1) * HB)
                                        : (g_H2 + (s - 2) * HB);
            *(float4*)&dst[r_b * 1024 + r_nbase + r_nl4] = make_float4(
                rnd_tf32(tanhf(sum.x)), rnd_tf32(tanhf(sum.y)),
                rnd_tf32(tanhf(sum.z)), rnd_tf32(tanhf(sum.w)));
        }
        gbar(2 * s + 1, nblk);
    }
}

// out[l][b][i] = sum_h hs[b][h]*Wo[i][h] + bo[i]
__global__ void __launch_bounds__(256) out_kernel(const float* __restrict__ Wo,
                                                  const float* __restrict__ bo,
                                                  float* __restrict__ out) {
    __shared__ float Hs[64][65];
    __shared__ float Wos[32][65];
    const int l = blockIdx.y, ibase = blockIdx.x * 32;
    const float* hsrc = (l == 0) ? g_H0 + 256 * HB : (l == 1) ? g_H1 + 255 * HB : g_H2 + 255 * HB;
    const int tid = threadIdx.x, i = tid & 31, brow = tid >> 5;
    float acc[8];
#pragma unroll
    for (int q = 0; q < 8; q++) acc[q] = 0.f;
    for (int kc = 0; kc < 1024; kc += 64) {
        __syncthreads();
#pragma unroll
        for (int j = 0; j < 16; j++) {
            int e = j * 256 + tid, b = e >> 6, k = e & 63;
            Hs[b][k] = hsrc[b * 1024 + kc + k];
        }
#pragma unroll
        for (int j = 0; j < 8; j++) {
            int e = j * 256 + tid, ii = e >> 6, k = e & 63;
            Wos[ii][k] = Wo[(ibase + ii) * 1024 + kc + k];
        }
        __syncthreads();
#pragma unroll
        for (int k = 0; k < 64; k++) {
            float w = Wos[i][k];
#pragma unroll
            for (int bb = 0; bb < 8; bb++) acc[bb] += Hs[bb * 8 + brow][k] * w;
        }
    }
    float bv = bo[ibase + i];
#pragma unroll
    for (int bb = 0; bb < 8; bb++)
        out[l * 32768 + (bb * 8 + brow) * 512 + ibase + i] = acc[bb] + bv;
}

extern "C" void kernel_launch(void* const* d_in, const int* in_sizes, int n_in,
                              void* d_out, int out_size) {
    const float* x     = (const float*)d_in[0];
    const float* noise = (const float*)d_in[1];
    const float* Wi0   = (const float*)d_in[2];
    const float* Wi12  = (const float*)d_in[3];
    const float* bi    = (const float*)d_in[4];
    const float* Ws    = (const float*)d_in[5];
    const float* bs    = (const float*)d_in[6];
    const float* Wh    = (const float*)d_in[7];
    const float* bh    = (const float*)d_in[8];
    const float* Wo    = (const float*)d_in[9];
    const float* bo    = (const float*)d_in[10];
    float* out = (float*)d_out;

    int dev = 0, sm = 148;
    cudaGetDevice(&dev);
    cudaDeviceGetAttribute(&sm, cudaDevAttrMultiProcessorCount, dev);
    int nblk = sm;
    if (nblk > 296) nblk = 296;
    if (nblk < 1) nblk = 1;

    int maxu = (NU + nblk - 1) / nblk;            // max weight units per block
    size_t smemB = (size_t)(2 * 64 * PAD + (maxu + 1) * UFLOATS) * sizeof(float);
    static int smem_set = 0;
    if (!smem_set) {
        cudaFuncSetAttribute(persist_kernel,
                             cudaFuncAttributeMaxDynamicSharedMemorySize, (int)smemB);
        smem_set = 1;
    }

    prep_kernel<<<512, 256>>>(Wi0, Wi12, bi, Ws, bs, Wh, bh, noise);
    xcomb_kernel<<<24576, 256>>>(x);
    gemmA_mma_kernel<<<dim3(8, 256, 3), 256>>>();
    persist_kernel<<<nblk, 512, smemB>>>(nblk);
    out_kernel<<<dim3(16, 3), 256>>>(Wo, bo, out);
}